// round 4
// baseline (speedup 1.0000x reference)
#include <cuda_runtime.h>

// ---------------- constants ----------------
#define C_NUM   80
#define TOPK_N  1000
#define CONF_T  0.05f
#define NMS_THR 0.6f
#define IMG_INV (1.0f/2048.0f)
#define HBINS   16384
#define CAND_CAP 32768
#define SORT_CAP 16384
#define N_ALL   3000
#define ROWS0   196608
#define ROWS1   49152
#define ROWS2   12288
#define RTOT    258048
#define GRID1   888      // 148 SMs x 6 blocks (residency-guaranteed)
#define TPB1    256
#define GRID2   80
#define TPB2    1024

// ---------------- device scratch ----------------
__device__ float              g_b[RTOT];
__device__ unsigned int       g_hist[3 * HBINS];
__device__ unsigned int       g_cnt[3];
__device__ unsigned int       g_Tbits[3];
__device__ unsigned long long g_cand[3][CAND_CAP];
__device__ unsigned long long g_topk[3][TOPK_N];
__device__ float   g_sscore[N_ALL];
__device__ int     g_slabel[N_ALL];
__device__ float4  g_sbox[N_ALL];
__device__ unsigned int g_barA, g_barB, g_barC, g_barD;

__device__ __forceinline__ float sigm(float x) { return 1.0f / (1.0f + expf(-x)); }

__device__ __forceinline__ void level_of(int grow, int& lvl, int& r) {
    if (grow < ROWS0)              { lvl = 0; r = grow; }
    else if (grow < ROWS0 + ROWS1) { lvl = 1; r = grow - ROWS0; }
    else                           { lvl = 2; r = grow - ROWS0 - ROWS1; }
}

// Grid-wide spin barrier. Requires all blocks resident (single wave).
__device__ __forceinline__ void gbar(unsigned int* c, unsigned int tgt) {
    __syncthreads();
    if (threadIdx.x == 0) {
        __threadfence();
        atomicAdd(c, 1u);
        while (*(volatile unsigned int*)c < tgt) __nanosleep(64);
        __threadfence();
    }
    __syncthreads();
}

__device__ void bitonic_desc(unsigned long long* s, int n) {
    for (int k = 2; k <= n; k <<= 1) {
        for (int j = k >> 1; j > 0; j >>= 1) {
            for (int t = threadIdx.x; t < n; t += blockDim.x) {
                int l = t ^ j;
                if (l > t) {
                    unsigned long long a = s[t], b = s[l];
                    bool dir = ((t & k) == 0);
                    if (dir ? (a < b) : (a > b)) { s[t] = b; s[l] = a; }
                }
            }
            __syncthreads();
        }
    }
}

// ============ K1: rowmax -> findT -> compact (persistent, 2 barriers) ============
__global__ __launch_bounds__(TPB1, 6)
void k1_select(const float* __restrict__ obj0, const float* __restrict__ cls0,
               const float* __restrict__ obj1, const float* __restrict__ cls1,
               const float* __restrict__ obj2, const float* __restrict__ cls2) {
    if (blockIdx.x == 0 && threadIdx.x == 0) { g_barC = 0u; g_barD = 0u; }

    // ---- phase A: per-anchor max-class bound + histogram (4 threads/row) ----
    for (int g = blockIdx.x * TPB1 + threadIdx.x; g < RTOT * 4; g += GRID1 * TPB1) {
        int grow = g >> 2;
        int sub = g & 3;
        int lvl, r;
        level_of(grow, lvl, r);
        const float* cls = (lvl == 0) ? cls0 : ((lvl == 1) ? cls1 : cls2);
        const float4* c4 = reinterpret_cast<const float4*>(cls) + (size_t)r * 20;
        float mx = -1e30f;
#pragma unroll
        for (int it = 0; it < 5; it++) {
            float4 v = c4[it * 4 + sub];
            mx = fmaxf(mx, fmaxf(fmaxf(v.x, v.y), fmaxf(v.z, v.w)));
        }
        mx = fmaxf(mx, __shfl_xor_sync(0xFFFFFFFFu, mx, 1));
        mx = fmaxf(mx, __shfl_xor_sync(0xFFFFFFFFu, mx, 2));
        if (sub == 0) {
            const float* obj = (lvl == 0) ? obj0 : ((lvl == 1) ? obj1 : obj2);
            float b = sqrtf(sigm(obj[r]) * sigm(mx));
            g_b[grow] = b;
            atomicAdd(&g_hist[lvl * HBINS + (__float_as_uint(b) >> 16)], 1u);
        }
    }

    gbar(&g_barA, GRID1);

    // ---- phase B: per-level threshold (blocks 0..2) ----
    __shared__ unsigned int csum[256];
    __shared__ unsigned int cbins[64];
    __shared__ int s_ch;
    __shared__ unsigned int s_cum;
    if (blockIdx.x < 3) {
        int lvl = blockIdx.x;
        unsigned int s = 0;
        int base = lvl * HBINS + threadIdx.x * 64;
#pragma unroll 8
        for (int i = 0; i < 64; i++) s += g_hist[base + i];
        csum[threadIdx.x] = s;
        __syncthreads();
        if (threadIdx.x == 0) {
            unsigned int cum = 0;
            int ch = 255;
            for (; ch > 0; ch--) {
                if (cum + csum[ch] >= TOPK_N) break;
                cum += csum[ch];
            }
            s_ch = ch;
            s_cum = cum;
        }
        __syncthreads();
        int ch = s_ch;
        if (threadIdx.x < 64)
            cbins[threadIdx.x] = g_hist[lvl * HBINS + ch * 64 + threadIdx.x];
        __syncthreads();
        if (threadIdx.x == 0) {
            unsigned int cum = s_cum;
            int bin = 63;
            for (; bin > 0; bin--) {
                cum += cbins[bin];
                if (cum >= TOPK_N) break;
            }
            g_Tbits[lvl] = ((unsigned int)(ch * 64 + bin)) << 16;
            g_cnt[lvl] = 0u;
        }
    }

    gbar(&g_barB, GRID1);

    // ---- phase C: sparse expansion, 1 thread per row ----
    __shared__ unsigned int sT[3];
    if (threadIdx.x < 3) sT[threadIdx.x] = *(volatile unsigned int*)&g_Tbits[threadIdx.x];
    __syncthreads();
    for (int grow = blockIdx.x * TPB1 + threadIdx.x; grow < RTOT; grow += GRID1 * TPB1) {
        int lvl, r;
        level_of(grow, lvl, r);
        unsigned int T = sT[lvl];
        unsigned int bb = __float_as_uint(g_b[grow]);
        if (bb + 64u < T) continue;
        const float* obj = (lvl == 0) ? obj0 : ((lvl == 1) ? obj1 : obj2);
        const float* cls = (lvl == 0) ? cls0 : ((lvl == 1) ? cls1 : cls2);
        float so = sigm(obj[r]);
        const float4* c4 = reinterpret_cast<const float4*>(cls) + (size_t)r * 20;
        for (int j = 0; j < 20; j++) {
            float4 v = c4[j];
            float vv[4] = {v.x, v.y, v.z, v.w};
#pragma unroll
            for (int k = 0; k < 4; k++) {
                unsigned int sb = __float_as_uint(sqrtf(so * sigm(vv[k])));
                if (sb >= T) {
                    unsigned int p = atomicAdd(&g_cnt[lvl], 1u);
                    if (p < CAND_CAP) {
                        int idx = r * C_NUM + j * 4 + k;
                        g_cand[lvl][p] = ((unsigned long long)sb << 24) |
                                         (unsigned long long)(0xFFFFFF - idx);
                    }
                }
            }
        }
    }
}

// ============ K2: sorts -> fuse -> NMS (80 blocks, 2 barriers) ============
extern __shared__ unsigned long long dyn[];

__global__ __launch_bounds__(TPB2, 1)
void k2_finish(const float* __restrict__ r0, const float* __restrict__ r1,
               const float* __restrict__ r2, const float* __restrict__ anc,
               float* __restrict__ out) {
    if (blockIdx.x == 0 && threadIdx.x == 0) { g_barA = 0u; g_barB = 0u; }

    // zero histogram for next replay (cheap, parallel to sorts)
    for (int i = blockIdx.x * TPB2 + threadIdx.x; i < 3 * HBINS; i += GRID2 * TPB2)
        g_hist[i] = 0u;

    // ---- phase 0: per-level candidate sort (blocks 0..2) ----
    if (blockIdx.x < 3) {
        int lvl = blockIdx.x;
        unsigned int cnt = *(volatile unsigned int*)&g_cnt[lvl];
        if (cnt > CAND_CAP) cnt = CAND_CAP;
        int n = 1024;
        while (n < (int)cnt) n <<= 1;
        if (n <= SORT_CAP) {
            for (int i = threadIdx.x; i < n; i += TPB2)
                dyn[i] = (i < (int)cnt) ? g_cand[lvl][i] : 0ULL;
            __syncthreads();
            bitonic_desc(dyn, n);
            for (int i = threadIdx.x; i < TOPK_N; i += TPB2)
                g_topk[lvl][i] = dyn[i];
        } else {
            for (int i = (int)cnt + (int)threadIdx.x; i < n; i += TPB2)
                g_cand[lvl][i] = 0ULL;
            __syncthreads();
            bitonic_desc(g_cand[lvl], n);
            for (int i = threadIdx.x; i < TOPK_N; i += TPB2)
                g_topk[lvl][i] = g_cand[lvl][i];
        }
    }

    gbar(&g_barC, GRID2);

    // ---- phase 1: decode + global stable sort + box/label output (block 0) ----
    if (blockIdx.x == 0) {
        unsigned long long* sh = dyn;                                   // 4096 * 8 B
        int* slab = (int*)(dyn + 4096);                                 // 3000 * 4 B
        float4* sbox = (float4*)((char*)(void*)dyn + 44800);            // 3000 * 16 B
        for (int i = threadIdx.x; i < 4096; i += TPB2) {
            if (i < N_ALL) {
                int lvl = i / TOPK_N;
                unsigned long long key = g_topk[lvl][i - lvl * TOPK_N];
                unsigned int sb = (unsigned int)(key >> 24);
                int idx = 0xFFFFFF - (int)(key & 0xFFFFFFULL);
                int c = idx % C_NUM;
                int m = idx / C_NUM;
                int a = m % 3;
                int cell = m / 3;
                int W = (lvl == 0) ? 256 : ((lvl == 1) ? 128 : 64);
                float stride = (lvl == 0) ? 8.0f : ((lvl == 1) ? 16.0f : 32.0f);
                int x = cell % W, y = cell / W;
                const float* reg = ((lvl == 0) ? r0 : ((lvl == 1) ? r1 : r2)) + (size_t)m * 4;
                float cx = ((float)x + 0.5f) * stride + (sigm(reg[0]) * 3.0f - 1.5f) * stride;
                float cy = ((float)y + 0.5f) * stride + (sigm(reg[1]) * 3.0f - 1.5f) * stride;
                float bw = expf(reg[2]) * anc[lvl * 6 + a * 2 + 0];
                float bh = expf(reg[3]) * anc[lvl * 6 + a * 2 + 1];
                float4 b;
                b.x = cx - 0.5f * bw; b.y = cy - 0.5f * bh;
                b.z = cx + 0.5f * bw; b.w = cy + 0.5f * bh;
                sbox[i] = b;
                slab[i] = c;
                float s = __uint_as_float(sb);
                s = (s > CONF_T) ? s : 0.0f;
                sh[i] = ((unsigned long long)__float_as_uint(s) << 12) |
                        (unsigned long long)(4095 - i);
            } else {
                sh[i] = 0ULL;
            }
        }
        __syncthreads();
        bitonic_desc(sh, 4096);
        for (int i = threadIdx.x; i < N_ALL; i += TPB2) {
            unsigned long long k = sh[i];
            int p = 4095 - (int)(k & 0xFFFULL);
            float s = __uint_as_float((unsigned int)(k >> 12));
            float4 b = sbox[p];
            g_sbox[i] = b;
            g_sscore[i] = s;
            g_slabel[i] = slab[p];
            out[i * 4 + 0] = fminf(fmaxf(b.x * IMG_INV, 0.0f), 1.0f);
            out[i * 4 + 1] = fminf(fmaxf(b.y * IMG_INV, 0.0f), 1.0f);
            out[i * 4 + 2] = fminf(fmaxf(b.z * IMG_INV, 0.0f), 1.0f);
            out[i * 4 + 3] = fminf(fmaxf(b.w * IMG_INV, 0.0f), 1.0f);
            out[12000 + i] = 0.0f;
            out[15000 + i] = (float)slab[p];
        }
    }

    gbar(&g_barD, GRID2);

    // ---- phase 2: per-class greedy NMS (80 blocks) ----
    {
        int c = blockIdx.x;
        float4* s_box = (float4*)(void*)dyn;                  // 1024 * 16 B
        int*    s_pos = (int*)((char*)(void*)dyn + 16384);    // 1024 * 4 B
        float*  s_area = (float*)((char*)(void*)dyn + 20480); // 1024 * 4 B
        float*  s_scr  = (float*)((char*)(void*)dyn + 24576); // 1024 * 4 B
        unsigned char* s_supp = (unsigned char*)((char*)(void*)dyn + 28672);
        __shared__ int s_n;
        __shared__ int s_wsum[32];
        if (threadIdx.x == 0) s_n = 0;
        __syncthreads();
        int lane = threadIdx.x & 31;
        int w = threadIdx.x >> 5;
        float offv = (float)c * 100000.0f;
        for (int base = 0; base < N_ALL; base += TPB2) {
            int i = base + threadIdx.x;
            bool pred = (i < N_ALL) && (g_slabel[i] == c) && (g_sscore[i] > CONF_T);
            unsigned int bal = __ballot_sync(0xFFFFFFFFu, pred);
            if (lane == 0) s_wsum[w] = __popc(bal);
            __syncthreads();
            int off = s_n;
            for (int ww = 0; ww < w; ww++) off += s_wsum[ww];
            int rank = off + __popc(bal & ((1u << lane) - 1u));
            if (pred && rank < 1024) {
                s_pos[rank] = i;
                float4 b = g_sbox[i];
                b.x += offv; b.y += offv; b.z += offv; b.w += offv;  // ref quantization
                s_box[rank] = b;
                s_area[rank] = (b.z - b.x) * (b.w - b.y);
                s_scr[rank] = g_sscore[i];
                s_supp[rank] = 0;
            }
            __syncthreads();
            if (threadIdx.x == 0) {
                int t = 0;
                for (int ww = 0; ww < 32; ww++) t += s_wsum[ww];
                s_n += t;
            }
            __syncthreads();
        }
        int n = (s_n < 1024) ? s_n : 1024;
        for (int a = 0; a < n; a++) {
            if (!s_supp[a]) {
                if (threadIdx.x == 0) out[12000 + s_pos[a]] = s_scr[a];
                float4 A = s_box[a];
                float arA = s_area[a];
                for (int b = a + 1 + (int)threadIdx.x; b < n; b += TPB2) {
                    if (s_supp[b]) continue;
                    float4 B = s_box[b];
                    float ltx = fmaxf(A.x, B.x), lty = fmaxf(A.y, B.y);
                    float rbx = fminf(A.z, B.z), rby = fminf(A.w, B.w);
                    float wx = fmaxf(rbx - ltx, 0.0f), wy = fmaxf(rby - lty, 0.0f);
                    float inter = wx * wy;
                    float iou = inter / (arA + s_area[b] - inter + 1e-12f);
                    if (iou > NMS_THR) s_supp[b] = 1;
                }
            }
            __syncthreads();
        }
    }
}

// ---------------- launcher ----------------
extern "C" void kernel_launch(void* const* d_in, const int* in_sizes, int n_in,
                              void* d_out, int out_size) {
    (void)in_sizes; (void)n_in; (void)out_size;
    const float* obj0 = (const float*)d_in[0];
    const float* cls0 = (const float*)d_in[1];
    const float* reg0 = (const float*)d_in[2];
    const float* obj1 = (const float*)d_in[3];
    const float* cls1 = (const float*)d_in[4];
    const float* reg1 = (const float*)d_in[5];
    const float* obj2 = (const float*)d_in[6];
    const float* cls2 = (const float*)d_in[7];
    const float* reg2 = (const float*)d_in[8];
    const float* anc  = (const float*)d_in[9];
    float* out = (float*)d_out;

    cudaFuncSetAttribute(k2_finish,
                         cudaFuncAttributeMaxDynamicSharedMemorySize, SORT_CAP * 8);

    k1_select<<<GRID1, TPB1>>>(obj0, cls0, obj1, cls1, obj2, cls2);
    k2_finish<<<GRID2, TPB2, SORT_CAP * 8>>>(reg0, reg1, reg2, anc, out);
}

// round 5
// speedup vs baseline: 1.9749x; 1.9749x over previous
#include <cuda_runtime.h>

// ---------------- constants ----------------
#define C_NUM   80
#define TOPK_N  1000
#define CONF_T  0.05f
#define NMS_THR 0.6f
#define IMG_INV (1.0f/2048.0f)
#define HBINS   16384
#define CAND_CAP 65536
#define N_ALL   3000
#define ROWS0   196608
#define ROWS1   49152
#define ROWS2   12288
#define RTOT    258048
#define GRID1   888      // 148 SMs x 6 blocks (residency-guaranteed with launch_bounds)
#define TPB1    256
#define GRID2   80
#define TPB2    1024
#define DYN2    32768

// ---------------- device scratch ----------------
__device__ float              g_b[RTOT];
__device__ unsigned int       g_hist[3 * HBINS];
__device__ unsigned int       g_cnt[3];
__device__ unsigned int       g_Tbin[3];
__device__ unsigned long long g_cand[3][CAND_CAP];
__device__ unsigned long long g_topk[3][TOPK_N];
__device__ float   g_sscore[N_ALL];
__device__ int     g_slabel[N_ALL];
__device__ float4  g_sbox[N_ALL];
__device__ unsigned int g_barA, g_barB, g_barC, g_barD;

__device__ __forceinline__ float sigm(float x) { return 1.0f / (1.0f + expf(-x)); }

__device__ __forceinline__ void level_of(int grow, int& lvl, int& r) {
    if (grow < ROWS0)              { lvl = 0; r = grow; }
    else if (grow < ROWS0 + ROWS1) { lvl = 1; r = grow - ROWS0; }
    else                           { lvl = 2; r = grow - ROWS0 - ROWS1; }
}

// Grid-wide spin barrier (all blocks resident, single wave).
__device__ __forceinline__ void gbar(unsigned int* c, unsigned int tgt) {
    __syncthreads();
    if (threadIdx.x == 0) {
        __threadfence();
        atomicAdd(c, 1u);
        while (*(volatile unsigned int*)c < tgt) __nanosleep(64);
        __threadfence();
    }
    __syncthreads();
}

__device__ void bitonic_desc(unsigned long long* s, int n) {
    for (int k = 2; k <= n; k <<= 1) {
        for (int j = k >> 1; j > 0; j >>= 1) {
            for (int t = threadIdx.x; t < n; t += blockDim.x) {
                int l = t ^ j;
                if (l > t) {
                    unsigned long long a = s[t], b = s[l];
                    bool dir = ((t & k) == 0);
                    if (dir ? (a < b) : (a > b)) { s[t] = b; s[l] = a; }
                }
            }
            __syncthreads();
        }
    }
}

// ============ K1: rowmax -> findT -> compact ============
__global__ __launch_bounds__(TPB1, 6)
void k1_select(const float* __restrict__ obj0, const float* __restrict__ cls0,
               const float* __restrict__ obj1, const float* __restrict__ cls1,
               const float* __restrict__ obj2, const float* __restrict__ cls2) {
    if (blockIdx.x == 0 && threadIdx.x == 0) { g_barC = 0u; g_barD = 0u; }

    // ---- phase A: per-anchor bound b + uniform-bin histogram (4 thr/row) ----
    for (int g = blockIdx.x * TPB1 + threadIdx.x; g < RTOT * 4; g += GRID1 * TPB1) {
        int grow = g >> 2;
        int sub = g & 3;
        int lvl, r;
        level_of(grow, lvl, r);
        const float* cls = (lvl == 0) ? cls0 : ((lvl == 1) ? cls1 : cls2);
        const float4* c4 = reinterpret_cast<const float4*>(cls) + (size_t)r * 20;
        float mx = -1e30f;
#pragma unroll
        for (int it = 0; it < 5; it++) {
            float4 v = c4[it * 4 + sub];
            mx = fmaxf(mx, fmaxf(fmaxf(v.x, v.y), fmaxf(v.z, v.w)));
        }
        mx = fmaxf(mx, __shfl_xor_sync(0xFFFFFFFFu, mx, 1));
        mx = fmaxf(mx, __shfl_xor_sync(0xFFFFFFFFu, mx, 2));
        if (sub == 0) {
            const float* obj = (lvl == 0) ? obj0 : ((lvl == 1) ? obj1 : obj2);
            float b = sqrtf(sigm(obj[r]) * sigm(mx));
            g_b[grow] = b;
            int bin = (int)(b * (float)HBINS);
            if (bin > HBINS - 1) bin = HBINS - 1;
            atomicAdd(&g_hist[lvl * HBINS + bin], 1u);
        }
    }

    gbar(&g_barA, GRID1);

    // ---- phase B: per-level threshold bin (blocks 0..2) ----
    __shared__ unsigned int csum[256];
    __shared__ unsigned int cbins[64];
    __shared__ int s_ch;
    __shared__ unsigned int s_cum;
    if (blockIdx.x < 3) {
        int lvl = blockIdx.x;
        unsigned int s = 0;
        int base = lvl * HBINS + threadIdx.x * 64;
#pragma unroll 8
        for (int i = 0; i < 64; i++) s += g_hist[base + i];
        csum[threadIdx.x] = s;
        __syncthreads();
        if (threadIdx.x == 0) {
            unsigned int cum = 0;
            int ch = 255;
            for (; ch > 0; ch--) {
                if (cum + csum[ch] >= TOPK_N) break;
                cum += csum[ch];
            }
            s_ch = ch;
            s_cum = cum;
        }
        __syncthreads();
        int ch = s_ch;
        if (threadIdx.x < 64)
            cbins[threadIdx.x] = g_hist[lvl * HBINS + ch * 64 + threadIdx.x];
        __syncthreads();
        if (threadIdx.x == 0) {
            unsigned int cum = s_cum;
            int bin = 63;
            for (; bin > 0; bin--) {
                cum += cbins[bin];
                if (cum >= TOPK_N) break;
            }
            g_Tbin[lvl] = (unsigned int)(ch * 64 + bin);
            g_cnt[lvl] = 0u;
        }
    }

    gbar(&g_barB, GRID1);

    // ---- phase C: sparse expansion, 1 thread/row ----
    __shared__ unsigned int sT[3];
    if (threadIdx.x < 3) sT[threadIdx.x] = *(volatile unsigned int*)&g_Tbin[threadIdx.x];
    __syncthreads();
    for (int grow = blockIdx.x * TPB1 + threadIdx.x; grow < RTOT; grow += GRID1 * TPB1) {
        int lvl, r;
        level_of(grow, lvl, r);
        int B = (int)sT[lvl];
        // identical discretization as phase A -> exact superset guarantee
        if ((int)(g_b[grow] * (float)HBINS) < B) continue;
        const float* obj = (lvl == 0) ? obj0 : ((lvl == 1) ? obj1 : obj2);
        const float* cls = (lvl == 0) ? cls0 : ((lvl == 1) ? cls1 : cls2);
        float so = sigm(obj[r]);
        const float4* c4 = reinterpret_cast<const float4*>(cls) + (size_t)r * 20;
        for (int j = 0; j < 20; j++) {
            float4 v = c4[j];
            float vv[4] = {v.x, v.y, v.z, v.w};
#pragma unroll
            for (int k = 0; k < 4; k++) {
                float s = sqrtf(so * sigm(vv[k]));
                if ((int)(s * (float)HBINS) >= B) {
                    unsigned int p = atomicAdd(&g_cnt[lvl], 1u);
                    if (p < CAND_CAP) {
                        int idx = r * C_NUM + j * 4 + k;
                        g_cand[lvl][p] = ((unsigned long long)__float_as_uint(s) << 24) |
                                         (unsigned long long)(0xFFFFFF - idx);
                    }
                }
            }
        }
    }
}

// ============ K2: radix-select+sort -> merge/decode -> NMS ============
extern __shared__ unsigned long long dyn[];

__global__ __launch_bounds__(TPB2, 1)
void k2_finish(const float* __restrict__ r0, const float* __restrict__ r1,
               const float* __restrict__ r2, const float* __restrict__ anc,
               float* __restrict__ out) {
    int tid = threadIdx.x;
    if (blockIdx.x == 0 && tid == 0) { g_barA = 0u; g_barB = 0u; }

    __shared__ unsigned int hist[256];
    __shared__ unsigned int s_chunk[8];
    __shared__ int s_v;
    __shared__ unsigned int s_wantnew, s_histv, s_m;
    __shared__ float s_anc[18];

    // ---- phase 0 ----
    if (blockIdx.x >= 3) {
        // zero histogram for next replay
        for (int i = (blockIdx.x - 3) * TPB2 + tid; i < 3 * HBINS; i += (GRID2 - 3) * TPB2)
            g_hist[i] = 0u;
    } else {
        int lvl = blockIdx.x;
        unsigned int cnt = *(volatile unsigned int*)&g_cnt[lvl];
        if (cnt > CAND_CAP) cnt = CAND_CAP;
        const unsigned long long* cand = g_cand[lvl];

        // exact MSB radix select of the 1000th-largest unique key
        unsigned long long prefix = 0ULL, mask = 0ULL;
        unsigned int want = TOPK_N;
        bool done = false;
        for (int p = 7; p >= 0 && !done; p--) {
            for (int i = tid; i < 256; i += TPB2) hist[i] = 0u;
            __syncthreads();
            int sh = p * 8;
            for (int i = tid; i < (int)cnt; i += TPB2) {
                unsigned long long k = cand[i];
                if ((k & mask) == prefix)
                    atomicAdd(&hist[(unsigned int)((k >> sh) & 255ULL)], 1u);
            }
            __syncthreads();
            if (tid < 256) {
                unsigned int ws = hist[tid];
                for (int o = 16; o > 0; o >>= 1)
                    ws += __shfl_down_sync(0xFFFFFFFFu, ws, o);
                if ((tid & 31) == 0) s_chunk[tid >> 5] = ws;
            }
            __syncthreads();
            if (tid == 0) {
                unsigned int cum = 0;
                int ch = 7;
                for (; ch > 0; ch--) {
                    if (cum + s_chunk[ch] >= want) break;
                    cum += s_chunk[ch];
                }
                int v = ch * 32 + 31;
                for (; v > ch * 32; v--) {
                    if (cum + hist[v] >= want) break;
                    cum += hist[v];
                }
                s_v = v;
                s_wantnew = want - cum;
                s_histv = hist[v];
            }
            __syncthreads();
            prefix |= ((unsigned long long)s_v) << sh;
            mask   |= 0xFFULL << sh;
            want = s_wantnew;
            if (want == s_histv) done = true;  // K* = prefix (low bits 0)
            __syncthreads();
        }
        unsigned long long Kstar = prefix;

        // compact exactly the TOPK_N keys >= Kstar, then sort 1024
        unsigned long long* keys = dyn;
        if (tid == 0) s_m = 0u;
        __syncthreads();
        for (int i = tid; i < (int)cnt; i += TPB2) {
            unsigned long long k = cand[i];
            if (k >= Kstar) {
                unsigned int p = atomicAdd(&s_m, 1u);
                if (p < 1024u) keys[p] = k;
            }
        }
        __syncthreads();
        if (tid >= (int)min(s_m, 1024u) && tid < 1024) keys[tid] = 0ULL;
        __syncthreads();
        bitonic_desc(keys, 1024);
        for (int i = tid; i < TOPK_N; i += TPB2)
            g_topk[lvl][i] = keys[i];
    }

    gbar(&g_barC, GRID2);

    // ---- phase 1: decode + merge-rank (block 0) ----
    if (blockIdx.x == 0) {
        unsigned long long* s_gk = dyn;  // 3000 composite keys
        if (tid < 18) s_anc[tid] = anc[tid];
        for (int i = tid; i < N_ALL; i += TPB2) {
            int lvl = i / TOPK_N;
            int r = i - lvl * TOPK_N;
            unsigned long long key = g_topk[lvl][r];
            unsigned int sb = (unsigned int)(key >> 24);
            float s = __uint_as_float(sb);
            unsigned int zs = (s > CONF_T) ? sb : 0u;
            s_gk[i] = ((unsigned long long)zs << 12) | (unsigned long long)(4095 - i);
        }
        __syncthreads();
        for (int i = tid; i < N_ALL; i += TPB2) {
            int lvl = i / TOPK_N;
            int r = i - lvl * TOPK_N;
            unsigned long long key = g_topk[lvl][r];
            unsigned long long gk = s_gk[i];
            int rank = r;  // own level: strictly-descending keys
#pragma unroll
            for (int l = 0; l < 3; l++) {
                if (l == lvl) continue;
                const unsigned long long* arr = s_gk + l * TOPK_N;
                int lo = 0, hi = TOPK_N;
                while (lo < hi) {
                    int mid = (lo + hi) >> 1;
                    if (arr[mid] > gk) lo = mid + 1; else hi = mid;
                }
                rank += lo;
            }
            // decode
            int idx = 0xFFFFFF - (int)(key & 0xFFFFFFULL);
            int c = idx % C_NUM;
            int m = idx / C_NUM;
            int a = m % 3;
            int cell = m / 3;
            int W = (lvl == 0) ? 256 : ((lvl == 1) ? 128 : 64);
            float stride = (lvl == 0) ? 8.0f : ((lvl == 1) ? 16.0f : 32.0f);
            int x = cell % W, y = cell / W;
            const float* reg = ((lvl == 0) ? r0 : ((lvl == 1) ? r1 : r2)) + (size_t)m * 4;
            float cx = ((float)x + 0.5f) * stride + (sigm(reg[0]) * 3.0f - 1.5f) * stride;
            float cy = ((float)y + 0.5f) * stride + (sigm(reg[1]) * 3.0f - 1.5f) * stride;
            float bw = expf(reg[2]) * s_anc[lvl * 6 + a * 2 + 0];
            float bh = expf(reg[3]) * s_anc[lvl * 6 + a * 2 + 1];
            float4 b;
            b.x = cx - 0.5f * bw; b.y = cy - 0.5f * bh;
            b.z = cx + 0.5f * bw; b.w = cy + 0.5f * bh;
            float szero = __uint_as_float((unsigned int)(gk >> 12));
            g_sbox[rank] = b;
            g_sscore[rank] = szero;
            g_slabel[rank] = c;
            out[rank * 4 + 0] = fminf(fmaxf(b.x * IMG_INV, 0.0f), 1.0f);
            out[rank * 4 + 1] = fminf(fmaxf(b.y * IMG_INV, 0.0f), 1.0f);
            out[rank * 4 + 2] = fminf(fmaxf(b.z * IMG_INV, 0.0f), 1.0f);
            out[rank * 4 + 3] = fminf(fmaxf(b.w * IMG_INV, 0.0f), 1.0f);
            out[12000 + rank] = 0.0f;
            out[15000 + rank] = (float)c;
        }
    }

    gbar(&g_barD, GRID2);

    // ---- phase 2: per-class greedy NMS (80 blocks) ----
    {
        int c = blockIdx.x;
        float4* s_box = (float4*)(void*)dyn;                  // 16384 B
        int*    s_pos = (int*)((char*)(void*)dyn + 16384);
        float*  s_area = (float*)((char*)(void*)dyn + 20480);
        float*  s_scr  = (float*)((char*)(void*)dyn + 24576);
        unsigned char* s_supp = (unsigned char*)((char*)(void*)dyn + 28672);
        __shared__ int s_n;
        __shared__ int s_wsum[32];
        if (tid == 0) s_n = 0;
        __syncthreads();
        int lane = tid & 31;
        int w = tid >> 5;
        float offv = (float)c * 100000.0f;
        for (int base = 0; base < N_ALL; base += TPB2) {
            int i = base + tid;
            bool pred = (i < N_ALL) && (g_slabel[i] == c) && (g_sscore[i] > CONF_T);
            unsigned int bal = __ballot_sync(0xFFFFFFFFu, pred);
            if (lane == 0) s_wsum[w] = __popc(bal);
            __syncthreads();
            int off = s_n;
            for (int ww = 0; ww < w; ww++) off += s_wsum[ww];
            int rank = off + __popc(bal & ((1u << lane) - 1u));
            if (pred && rank < 1024) {
                s_pos[rank] = i;
                float4 b = g_sbox[i];
                b.x += offv; b.y += offv; b.z += offv; b.w += offv;  // ref quantization
                s_box[rank] = b;
                s_area[rank] = (b.z - b.x) * (b.w - b.y);
                s_scr[rank] = g_sscore[i];
                s_supp[rank] = 0;
            }
            __syncthreads();
            if (tid == 0) {
                int t = 0;
                for (int ww = 0; ww < 32; ww++) t += s_wsum[ww];
                s_n += t;
            }
            __syncthreads();
        }
        int n = (s_n < 1024) ? s_n : 1024;
        for (int a = 0; a < n; a++) {
            if (!s_supp[a]) {
                if (tid == 0) out[12000 + s_pos[a]] = s_scr[a];
                float4 A = s_box[a];
                float arA = s_area[a];
                for (int b = a + 1 + tid; b < n; b += TPB2) {
                    if (s_supp[b]) continue;
                    float4 B = s_box[b];
                    float ltx = fmaxf(A.x, B.x), lty = fmaxf(A.y, B.y);
                    float rbx = fminf(A.z, B.z), rby = fminf(A.w, B.w);
                    float wx = fmaxf(rbx - ltx, 0.0f), wy = fmaxf(rby - lty, 0.0f);
                    float inter = wx * wy;
                    float iou = inter / (arA + s_area[b] - inter + 1e-12f);
                    if (iou > NMS_THR) s_supp[b] = 1;
                }
            }
            __syncthreads();
        }
    }
}

// ---------------- launcher ----------------
extern "C" void kernel_launch(void* const* d_in, const int* in_sizes, int n_in,
                              void* d_out, int out_size) {
    (void)in_sizes; (void)n_in; (void)out_size;
    const float* obj0 = (const float*)d_in[0];
    const float* cls0 = (const float*)d_in[1];
    const float* reg0 = (const float*)d_in[2];
    const float* obj1 = (const float*)d_in[3];
    const float* cls1 = (const float*)d_in[4];
    const float* reg1 = (const float*)d_in[5];
    const float* obj2 = (const float*)d_in[6];
    const float* cls2 = (const float*)d_in[7];
    const float* reg2 = (const float*)d_in[8];
    const float* anc  = (const float*)d_in[9];
    float* out = (float*)d_out;

    cudaFuncSetAttribute(k2_finish,
                         cudaFuncAttributeMaxDynamicSharedMemorySize, DYN2);

    k1_select<<<GRID1, TPB1>>>(obj0, cls0, obj1, cls1, obj2, cls2);
    k2_finish<<<GRID2, TPB2, DYN2>>>(reg0, reg1, reg2, anc, out);
}